// round 2
// baseline (speedup 1.0000x reference)
#include <cuda_runtime.h>

#define B   128
#define R   1152
#define J   10
#define D   16
#define JD  160
#define CIN 8

// ---- scratch (device globals; allocation inside kernel_launch is forbidden) ----
__device__ float g_uhat[(size_t)B * R * JD];  // 94.4 MB
__device__ float g_s[B * JD];
__device__ float g_v[B * JD];
__device__ float g_b[R * J];
__device__ float g_c[R * J];

// ---------------------------------------------------------------------------
// K1: u_hat[b,r,jd] = dot(W[r,jd,0:8], x[b,r,0:8]); also accumulate
// s1 partial with uniform c = 1/10 (softmax of zeros).
// grid (R/16, B), block 160 (one thread per (j,d))
// ---------------------------------------------------------------------------
__global__ void k_uhat(const float* __restrict__ x, const float* __restrict__ W) {
    const int RT = 16;
    int b  = blockIdx.y;
    int r0 = blockIdx.x * RT;
    int jd = threadIdx.x;

    __shared__ float xs[RT][CIN];
    if (jd < RT * CIN)
        xs[jd >> 3][jd & 7] = x[((size_t)b * R + r0 + (jd >> 3)) * CIN + (jd & 7)];
    __syncthreads();

    float acc = 0.f;
#pragma unroll 4
    for (int rr = 0; rr < RT; rr++) {
        int r = r0 + rr;
        const float4* wp = reinterpret_cast<const float4*>(W + ((size_t)r * JD + jd) * CIN);
        float4 w0 = wp[0];
        float4 w1 = wp[1];
        float u = w0.x * xs[rr][0] + w0.y * xs[rr][1] + w0.z * xs[rr][2] + w0.w * xs[rr][3]
                + w1.x * xs[rr][4] + w1.y * xs[rr][5] + w1.z * xs[rr][6] + w1.w * xs[rr][7];
        g_uhat[((size_t)b * R + r) * JD + jd] = u;
        acc += u;
    }
    atomicAdd(&g_s[b * JD + jd], 0.1f * acc);
}

// ---------------------------------------------------------------------------
// K2: squash. v = s * sqrt(|s|^2) / (1 + |s|^2), norm over d (16 lanes).
// grid B, block 160. Writes to `out` (g_v or d_out on the final iteration).
// ---------------------------------------------------------------------------
__global__ void k_squash(float* __restrict__ out) {
    int b  = blockIdx.x;
    int jd = threadIdx.x;
    float s  = g_s[b * JD + jd];
    float sq = s * s;
#pragma unroll
    for (int o = 8; o >= 1; o >>= 1)
        sq += __shfl_xor_sync(0xffffffffu, sq, o, 16);
    float scale = sqrtf(sq) / (1.f + sq);
    out[b * JD + jd] = s * scale;
}

// ---------------------------------------------------------------------------
// K3: delta_b[r,j] = mean_b sum_d u_hat[b,r,j,d] * v[b,j,d];
//     b_ij (+)= delta;  c = softmax_j(b_ij)   (c is for the NEXT iteration)
// grid R, block 160.  first==1: previous b_ij is zero (written, not read).
// ---------------------------------------------------------------------------
__global__ void k_delta(int first) {
    int r  = blockIdx.x;
    int jd = threadIdx.x;
    int j  = jd >> 4;
    int d  = jd & 15;

    const float* up = g_uhat + (size_t)r * JD + jd;
    const float* vp = g_v + jd;
    float acc = 0.f;
#pragma unroll 8
    for (int b = 0; b < B; b++)
        acc += up[(size_t)b * R * JD] * vp[b * JD];

#pragma unroll
    for (int o = 8; o >= 1; o >>= 1)
        acc += __shfl_xor_sync(0xffffffffu, acc, o, 16);

    __shared__ float bj[J];
    if (d == 0) {
        float nb = acc * (1.f / (float)B);
        if (!first) nb += g_b[r * J + j];
        g_b[r * J + j] = nb;
        bj[j] = nb;
    }
    __syncthreads();

    if (jd < J) {
        float m = -1e30f;
#pragma unroll
        for (int k = 0; k < J; k++) m = fmaxf(m, bj[k]);
        float denom = 0.f;
#pragma unroll
        for (int k = 0; k < J; k++) denom += expf(bj[k] - m);
        g_c[r * J + jd] = expf(bj[jd] - m) / denom;
    }
}

// ---------------------------------------------------------------------------
// K4: s[b,j,d] += sum_{r in chunk} c[r,j] * u_hat[b,r,j,d]
// grid (R/128, B), block 160. g_s must be zeroed beforehand (memset node).
// ---------------------------------------------------------------------------
__global__ void k_saccum() {
    const int RC = 128;
    int b  = blockIdx.y;
    int r0 = blockIdx.x * RC;
    int jd = threadIdx.x;
    int j  = jd >> 4;

    __shared__ float cs[RC * J];
    for (int i = jd; i < RC * J; i += JD)
        cs[i] = g_c[r0 * J + i];
    __syncthreads();

    const float* up = g_uhat + ((size_t)b * R + r0) * JD + jd;
    float acc = 0.f;
#pragma unroll 8
    for (int rr = 0; rr < RC; rr++)
        acc += cs[rr * J + j] * up[(size_t)rr * JD];

    atomicAdd(&g_s[b * JD + jd], acc);
}

// ---------------------------------------------------------------------------
extern "C" void kernel_launch(void* const* d_in, const int* in_sizes, int n_in,
                              void* d_out, int out_size) {
    const float* x = (const float*)d_in[0];
    const float* W = (const float*)d_in[1];
    if (n_in >= 2 && in_sizes[0] == R * J * D * CIN) {  // inputs arrived swapped
        x = (const float*)d_in[1];
        W = (const float*)d_in[0];
    }
    float* out = (float*)d_out;

    // Resolve device-global addresses on the HOST side. Passing a __device__
    // symbol directly as a kernel argument from host code is invalid (that was
    // the round-1 bug: v was written through a garbage pointer).
    void* s_addr = nullptr;
    void* v_addr = nullptr;
    cudaGetSymbolAddress(&s_addr, g_s);
    cudaGetSymbolAddress(&v_addr, g_v);
    float* v_dev = (float*)v_addr;

    dim3 guh(R / 16, B);
    dim3 gsa(R / 128, B);

    // iter 1: c uniform -> s1 fused into u_hat pass
    cudaMemsetAsync(s_addr, 0, B * JD * sizeof(float));
    k_uhat<<<guh, JD>>>(x, W);
    k_squash<<<B, JD>>>(v_dev);        // v1
    k_delta<<<R, JD>>>(1);             // b1, c2

    // iter 2
    cudaMemsetAsync(s_addr, 0, B * JD * sizeof(float));
    k_saccum<<<gsa, JD>>>();           // s2
    k_squash<<<B, JD>>>(v_dev);        // v2
    k_delta<<<R, JD>>>(0);             // b2, c3

    // iter 3
    cudaMemsetAsync(s_addr, 0, B * JD * sizeof(float));
    k_saccum<<<gsa, JD>>>();           // s3
    k_squash<<<B, JD>>>(out);          // v3 -> output [B, J, D, 1]
}

// round 4
// speedup vs baseline: 1.3390x; 1.3390x over previous
#include <cuda_runtime.h>

#define B_   128
#define R_   1152
#define J_   10
#define D_   16
#define JD_  160
#define CIN_ 8
#define GRID 144
#define RC   8      // routes per block (144*8 = 1152)
#define NT   320    // threads per block: (jd in [0,160)) x (bh in {0,1})

// ---- global scratch (device globals; no allocation allowed) ----
__device__ float g_part[(size_t)GRID * B_ * JD_];   // per-block s partials, 11.8 MB
__device__ float g_v[B_ * JD_];
__device__ unsigned g_cnt = 0;
__device__ volatile unsigned g_gen = 0;

// ---- smem layout (float offsets) ----
#define SW_OFF 0                         // W chunk: RC*160*8 = 10240 floats
#define SX_OFF 10240                     // x chunk packed f32x2: RC*64*8*2 = 8192 floats
#define SC_OFF (10240 + 8192)            // c[r][j]: RC*16 = 128
#define SB_OFF (SC_OFF + 128)            // b_ij[r][j]: 128
#define SD_OFF (SB_OFF + 128)            // delta reduce: 2*128 = 256
#define SMEM_FLOATS (SD_OFF + 256)
#define SMEM_BYTES  (SMEM_FLOATS * 4)    // 75776 B

// ---- packed f32x2 helpers ----
__device__ __forceinline__ unsigned long long pack2(float lo, float hi) {
    unsigned long long r;
    asm("mov.b64 %0, {%1, %2};" : "=l"(r)
        : "r"(__float_as_uint(lo)), "r"(__float_as_uint(hi)));
    return r;
}
__device__ __forceinline__ float2 unpack2(unsigned long long v) {
    unsigned lo, hi;
    asm("mov.b64 {%0, %1}, %2;" : "=r"(lo), "=r"(hi) : "l"(v));
    return make_float2(__uint_as_float(lo), __uint_as_float(hi));
}
__device__ __forceinline__ void ffma2(unsigned long long& d,
                                      unsigned long long a, unsigned long long b) {
    asm("fma.rn.f32x2 %0, %1, %2, %0;" : "+l"(d) : "l"(a), "l"(b));
}

// ---- one-wave grid barrier (all 144 blocks resident: 1 block/SM) ----
__device__ __forceinline__ void grid_sync(int t) {
    __syncthreads();
    if (t == 0) {
        __threadfence();
        unsigned gen = g_gen;
        if (atomicAdd(&g_cnt, 1u) == GRID - 1) {
            atomicExch(&g_cnt, 0u);
            __threadfence();
            g_gen = gen + 1;
        } else {
            while (g_gen == gen) { __nanosleep(64); }
        }
        __threadfence();
    }
    __syncthreads();
}

// ---------------------------------------------------------------------------
// s-phase: partial_s[b,jd] = sum_{r in chunk} coef(r,j) * u_hat[b,r,jd]
// coef = 0.1 (uniform, iter 1) or sC[r][j]. Writes g_part[blk].
// ---------------------------------------------------------------------------
__device__ __noinline__ void s_phase(float* sm, int jd, int bh, int j, int blk,
                                     int uniform) {
    const float* sW = sm + SW_OFF;
    const float* sX = sm + SX_OFF;
    const float* sC = sm + SC_OFF;

    unsigned long long acc[32];
#pragma unroll
    for (int bp = 0; bp < 32; bp++) acc[bp] = 0ull;

    for (int r = 0; r < RC; r++) {
        float coef = uniform ? 0.1f : sC[r * 16 + j];
        const float4* wp = (const float4*)(sW + (r * JD_ + jd) * CIN_);
        float4 wa = wp[0], wb = wp[1];
        unsigned long long w2[8];
        w2[0] = pack2(wa.x * coef, wa.x * coef);
        w2[1] = pack2(wa.y * coef, wa.y * coef);
        w2[2] = pack2(wa.z * coef, wa.z * coef);
        w2[3] = pack2(wa.w * coef, wa.w * coef);
        w2[4] = pack2(wb.x * coef, wb.x * coef);
        w2[5] = pack2(wb.y * coef, wb.y * coef);
        w2[6] = pack2(wb.z * coef, wb.z * coef);
        w2[7] = pack2(wb.w * coef, wb.w * coef);
        const ulonglong2* xq =
            (const ulonglong2*)(sX + (size_t)(r * 64 + bh * 32) * 16);
#pragma unroll
        for (int bp = 0; bp < 32; bp++) {
            ulonglong2 q0 = xq[bp * 4 + 0];
            ulonglong2 q1 = xq[bp * 4 + 1];
            ulonglong2 q2 = xq[bp * 4 + 2];
            ulonglong2 q3 = xq[bp * 4 + 3];
            ffma2(acc[bp], w2[0], q0.x);
            ffma2(acc[bp], w2[1], q0.y);
            ffma2(acc[bp], w2[2], q1.x);
            ffma2(acc[bp], w2[3], q1.y);
            ffma2(acc[bp], w2[4], q2.x);
            ffma2(acc[bp], w2[5], q2.y);
            ffma2(acc[bp], w2[6], q3.x);
            ffma2(acc[bp], w2[7], q3.y);
        }
    }

    float* gp = g_part + (size_t)blk * (B_ * JD_) + (size_t)bh * 64 * JD_ + jd;
#pragma unroll
    for (int bp = 0; bp < 32; bp++) {
        float2 u = unpack2(acc[bp]);
        gp[(2 * bp) * JD_]     = u.x;
        gp[(2 * bp + 1) * JD_] = u.y;
    }
}

// ---------------------------------------------------------------------------
// reduce + squash: s[i] = sum over 144 block partials; v = squash(s).
// Blocks 0..63 cover all 20480 outputs (one per thread).
// ---------------------------------------------------------------------------
__device__ __noinline__ void reduce_squash(float* tgt, int gt) {
    if (gt >= B_ * JD_) return;   // trims whole blocks only; shfl stays uniform
    float s = 0.f;
    const float* p = g_part + gt;
#pragma unroll 8
    for (int k = 0; k < GRID; k++) s += __ldcg(p + (size_t)k * (B_ * JD_));
    float sq = s * s;
#pragma unroll
    for (int o = 8; o; o >>= 1) sq += __shfl_xor_sync(0xffffffffu, sq, o, 16);
    tgt[gt] = s * (sqrtf(sq) / (1.f + sq));
}

// ---------------------------------------------------------------------------
// delta-phase (block-local): delta[r,j] = mean_b sum_d u_hat[b,r,jd]*v[b,jd];
// b_ij += delta; c = softmax_j(b_ij). b_ij/c live in smem (block owns routes).
// ---------------------------------------------------------------------------
__device__ __noinline__ void delta_phase(float* sm, int jd, int bh, int j,
                                         int first, int t) {
    const float* sW = sm + SW_OFF;
    const float* sX = sm + SX_OFF;
    float* sC = sm + SC_OFF;
    float* sB = sm + SB_OFF;
    float* sD = sm + SD_OFF;

    unsigned long long v2[32];
#pragma unroll
    for (int bp = 0; bp < 32; bp++) {
        int b = bh * 64 + 2 * bp;
        v2[bp] = pack2(__ldcg(&g_v[b * JD_ + jd]),
                       __ldcg(&g_v[b * JD_ + JD_ + jd]));
    }

    for (int r = 0; r < RC; r++) {
        const float4* wp = (const float4*)(sW + (r * JD_ + jd) * CIN_);
        float4 wa = wp[0], wb = wp[1];
        unsigned long long w2[8];
        w2[0] = pack2(wa.x, wa.x); w2[1] = pack2(wa.y, wa.y);
        w2[2] = pack2(wa.z, wa.z); w2[3] = pack2(wa.w, wa.w);
        w2[4] = pack2(wb.x, wb.x); w2[5] = pack2(wb.y, wb.y);
        w2[6] = pack2(wb.z, wb.z); w2[7] = pack2(wb.w, wb.w);
        const ulonglong2* xq =
            (const ulonglong2*)(sX + (size_t)(r * 64 + bh * 32) * 16);
        unsigned long long dacc = 0ull;
#pragma unroll
        for (int bp = 0; bp < 32; bp++) {
            ulonglong2 q0 = xq[bp * 4 + 0];
            ulonglong2 q1 = xq[bp * 4 + 1];
            ulonglong2 q2 = xq[bp * 4 + 2];
            ulonglong2 q3 = xq[bp * 4 + 3];
            unsigned long long u2 = 0ull;
            ffma2(u2, w2[0], q0.x);
            ffma2(u2, w2[1], q0.y);
            ffma2(u2, w2[2], q1.x);
            ffma2(u2, w2[3], q1.y);
            ffma2(u2, w2[4], q2.x);
            ffma2(u2, w2[5], q2.y);
            ffma2(u2, w2[6], q3.x);
            ffma2(u2, w2[7], q3.y);
            ffma2(dacc, u2, v2[bp]);
        }
        float2 dd = unpack2(dacc);
        float dr = dd.x + dd.y;
#pragma unroll
        for (int o = 8; o; o >>= 1) dr += __shfl_xor_sync(0xffffffffu, dr, o, 16);
        if ((jd & 15) == 0) sD[bh * 128 + r * 16 + j] = dr;  // unique slot
    }
    __syncthreads();

    if (t < RC) {
        int r = t;
        float bn[J_];
        float m = -1e30f;
#pragma unroll
        for (int q = 0; q < J_; q++) {
            float val = (sD[r * 16 + q] + sD[128 + r * 16 + q]) * (1.f / (float)B_);
            if (!first) val += sB[r * 16 + q];
            sB[r * 16 + q] = val;
            bn[q] = val;
            m = fmaxf(m, val);
        }
        float den = 0.f;
#pragma unroll
        for (int q = 0; q < J_; q++) den += expf(bn[q] - m);
        float inv = 1.f / den;
#pragma unroll
        for (int q = 0; q < J_; q++) sC[r * 16 + q] = expf(bn[q] - m) * inv;
    }
    __syncthreads();
}

// ---------------------------------------------------------------------------
__global__ void __launch_bounds__(NT, 1)
caps_kernel(const float* __restrict__ x, const float* __restrict__ W,
            float* __restrict__ out) {
    extern __shared__ float sm[];
    int t   = threadIdx.x;
    int blk = blockIdx.x;
    int jd  = t % JD_;
    int bh  = t / JD_;
    int j   = jd >> 4;
    int r0  = blk * RC;

    // Load W chunk (coalesced float4)
    const float4* Wg = (const float4*)(W + (size_t)r0 * JD_ * CIN_);
    float4* sW4 = (float4*)(sm + SW_OFF);
    for (int i = t; i < RC * JD_ * CIN_ / 4; i += NT) sW4[i] = Wg[i];

    // Load x chunk, packed as [r][b/2][c] float2 over batch pairs
    for (int i = t; i < RC * B_ * CIN_; i += NT) {
        int b  = i >> 6;
        int rc = i & 63;
        int r  = rc >> 3;
        int c  = rc & 7;
        float val = x[(size_t)b * (R_ * CIN_) + r0 * CIN_ + rc];
        sm[SX_OFF + ((r * 64 + (b >> 1)) * CIN_ + c) * 2 + (b & 1)] = val;
    }
    __syncthreads();

    int gt = blk * NT + t;

    // iter 1 (c uniform = 0.1)
    s_phase(sm, jd, bh, j, blk, 1);
    grid_sync(t);
    reduce_squash(g_v, gt);                 // v1
    grid_sync(t);

    // iter 2
    delta_phase(sm, jd, bh, j, 1, t);       // b1, c2 (block-local)
    s_phase(sm, jd, bh, j, blk, 0);         // s2 partials
    grid_sync(t);
    reduce_squash(g_v, gt);                 // v2
    grid_sync(t);

    // iter 3
    delta_phase(sm, jd, bh, j, 0, t);       // b2, c3
    s_phase(sm, jd, bh, j, blk, 0);         // s3 partials
    grid_sync(t);
    reduce_squash(out, gt);                 // v3 -> output [B,10,16,1]
}

// ---------------------------------------------------------------------------
extern "C" void kernel_launch(void* const* d_in, const int* in_sizes, int n_in,
                              void* d_out, int out_size) {
    const float* x = (const float*)d_in[0];
    const float* W = (const float*)d_in[1];
    if (n_in >= 2 && in_sizes[0] == R_ * J_ * D_ * CIN_) {  // inputs swapped
        x = (const float*)d_in[1];
        W = (const float*)d_in[0];
    }
    cudaFuncSetAttribute(caps_kernel,
                         cudaFuncAttributeMaxDynamicSharedMemorySize, SMEM_BYTES);
    caps_kernel<<<GRID, NT, SMEM_BYTES>>>(x, W, (float*)d_out);
}